// round 1
// baseline (speedup 1.0000x reference)
#include <cuda_runtime.h>

#define LFRAMES 120000
#define C       256
#define TL      64
#define NTH     256
#define TSAMP   600000

// ping-pong scratch for res_in between stages (static device arrays: allowed)
__device__ float g_bufA[LFRAMES * C];
__device__ float g_bufB[LFRAMES * C];

__device__ __forceinline__ float leakyf(float x) { return x >= 0.0f ? x : 0.3f * x; }

// quantize(x, scale, offset) = clip(round(x/scale - offset), -128, 127)
// jnp.round == round-half-to-even == rintf
__device__ __forceinline__ float quantf(float x, float s, float o) {
    float q = rintf(x / s - o);
    return fminf(fmaxf(q, -128.0f), 127.0f);
}

// -------------------------------------------------------------------------
// Kernel 1: first conv  (k=10, stride=5, cin=1 -> cout=256) + bias
// res_in[l][c] = b[c] + sum_k xp[5l+k] * w[k][c],  xp = concat(first_buffer, x)
// -------------------------------------------------------------------------
__global__ __launch_bounds__(NTH) void k_first(
    const float* __restrict__ x, const float* __restrict__ fb,
    const float* __restrict__ wf, const float* __restrict__ bf,
    float* __restrict__ out)
{
    __shared__ float sx[5 * TL + 10];
    const int l0  = blockIdx.x * TL;
    const int tid = threadIdx.x;
    const int base = 5 * l0;  // padded-coordinate start

    for (int i = tid; i < 5 * TL + 10; i += NTH) {
        int t = base + i;
        float v;
        if (t < 5)                 v = fb[t];
        else if (t - 5 < TSAMP)    v = x[t - 5];
        else                       v = 0.0f;
        sx[i] = v;
    }

    float w[10];
#pragma unroll
    for (int k = 0; k < 10; k++) w[k] = wf[k * C + tid];
    const float b = bf[tid];
    __syncthreads();

    for (int f = 0; f < TL; f++) {
        float acc = b;
#pragma unroll
        for (int k = 0; k < 10; k++) acc = fmaf(sx[5 * f + k], w[k], acc);
        out[(l0 + f) * C + tid] = acc;
    }
}

// -------------------------------------------------------------------------
// Shared-memory 256-deep GEMM: acc[8][8] += sIn[TL][256] @ Wg[256][256]
// thread (ty = tid>>5, tx = tid&31) owns rows ty*8..+7, cols tx*8..+7
// Weight chunks of 32 rows staged through sW (reused smem region).
// -------------------------------------------------------------------------
__device__ __forceinline__ void gemm256(
    float acc[8][8], const float* __restrict__ sIn, float* sW,
    const float* __restrict__ Wg, int ty, int tx, int tid)
{
    for (int kb = 0; kb < 8; kb++) {
        __syncthreads();  // previous users of sW are done
        const float4* wg  = (const float4*)(Wg + kb * 32 * C);
        float4*       sw4 = (float4*)sW;
#pragma unroll
        for (int i = 0; i < 8; i++) sw4[tid + i * NTH] = wg[tid + i * NTH];
        __syncthreads();

#pragma unroll 4
        for (int kk = 0; kk < 32; kk++) {
            const int k = kb * 32 + kk;
            float h[8];
#pragma unroll
            for (int i = 0; i < 8; i++) h[i] = sIn[(ty * 8 + i) * C + k];  // broadcast
            const float4* w4 = (const float4*)(sW + kk * C + tx * 8);
            float4 wa = w4[0], wb = w4[1];
            float wv[8] = {wa.x, wa.y, wa.z, wa.w, wb.x, wb.y, wb.z, wb.w};
#pragma unroll
            for (int i = 0; i < 8; i++)
#pragma unroll
                for (int j = 0; j < 8; j++)
                    acc[i][j] = fmaf(h[i], wv[j], acc[i][j]);
        }
    }
}

// -------------------------------------------------------------------------
// Fused residual block.
// MODE 1 (dil=1): ci=leaky(src); GEMM1 post: quantize(17.63,-67)+leaky;
//                 out = quantize(src + (o-16)*6.528, 12.716, -23)
// MODE 2 (dil=3): ci=quant(dequant(leaky(src_q)));  pad rows quantized too!
//                 GEMM1 post: leaky;  out = o + src
// MODE 3 (dil=9): ci=quant(dequant(leaky(src)));    pad rows quantized too!
//                 GEMM1 post: leaky;  out = (leaky(o+src)+34)*3.6989
// -------------------------------------------------------------------------
template <int MODE, int DIL>
__global__ __launch_bounds__(NTH) void k_block(
    const float* __restrict__ src,  const float* __restrict__ cbuf,
    const float* __restrict__ wdw,  const float* __restrict__ bdw,
    const float* __restrict__ wpw,  const float* __restrict__ bpw,
    const float* __restrict__ wlc,  const float* __restrict__ blc,
    float* __restrict__ dst)
{
    constexpr int PAD = 2 * DIL;
    constexpr float S2 = 5.548006534576416f;
    constexpr float S3 = 4.458680152893066f;

    extern __shared__ float sm[];
    float* sA = sm;                       // (TL+PAD)*C : ci, then W chunks
    float* sB = sm + (TL + PAD) * C;      // TL*C       : H, then P

    const int l0  = blockIdx.x * TL;
    const int tid = threadIdx.x;
    const int ty  = tid >> 5;
    const int tx  = tid & 31;

    // 1) build ci tile (rows t = l0-PAD .. l0+TL-1), channel = tid
    for (int row = 0; row < TL + PAD; row++) {
        const int t = l0 - PAD + row;
        float v;
        if (t < 0) {
            float bv = cbuf[(t + PAD) * C + tid];
            if (MODE == 1)      v = bv;                       // raw pad (block1)
            else if (MODE == 2) v = quantf(bv, S2, 47.0f);    // pad quantized after concat
            else                v = quantf(bv, S3, 38.0f);
        } else {
            float r = src[t * C + tid];
            if (MODE == 1) {
                v = leakyf(r);
            } else if (MODE == 2) {
                float d = (leakyf(r) + 47.0f) * S2;           // dequantize
                v = quantf(d, S2, 47.0f);                     // re-quantize
            } else {
                float d = (leakyf(r) + 38.0f) * S3;
                v = quantf(d, S3, 38.0f);
            }
        }
        sA[row * C + tid] = v;
    }
    __syncthreads();

    // 2) depthwise conv (k=3, dilation DIL) -> sB[r][c]
    {
        const float w0 = wdw[tid], w1 = wdw[C + tid], w2 = wdw[2 * C + tid];
        const float bb = bdw[tid];
        for (int r = 0; r < TL; r++) {
            float h = bb;
            h = fmaf(sA[r * C + tid],             w0, h);
            h = fmaf(sA[(r + DIL) * C + tid],     w1, h);
            h = fmaf(sA[(r + 2 * DIL) * C + tid], w2, h);
            sB[r * C + tid] = h;
        }
    }
    __syncthreads();

    // 3) GEMM1: P = H @ Wpw + bpw
    float acc[8][8];
#pragma unroll
    for (int i = 0; i < 8; i++)
#pragma unroll
        for (int j = 0; j < 8; j++) acc[i][j] = bpw[tx * 8 + j];
    gemm256(acc, sB, sA, wpw, ty, tx, tid);
    __syncthreads();  // all reads of sB (H) done

    // 3b) pointwise epilogue -> write P into sB
#pragma unroll
    for (int i = 0; i < 8; i++)
#pragma unroll
        for (int j = 0; j < 8; j++) {
            float p = acc[i][j];
            if (MODE == 1) p = quantf(p, 17.62967872619629f, -67.0f);
            p = leakyf(p);
            sB[(ty * 8 + i) * C + tx * 8 + j] = p;
        }
    __syncthreads();

    // 4) GEMM2: O = P @ Wlc + blc
#pragma unroll
    for (int i = 0; i < 8; i++)
#pragma unroll
        for (int j = 0; j < 8; j++) acc[i][j] = blc[tx * 8 + j];
    gemm256(acc, sB, sA, wlc, ty, tx, tid);

    // 5) residual + mode-specific output
#pragma unroll
    for (int i = 0; i < 8; i++) {
        const int l = l0 + ty * 8 + i;
#pragma unroll
        for (int j = 0; j < 8; j++) {
            const int c = tx * 8 + j;
            const float o = acc[i][j];
            const float r = src[l * C + c];
            float val;
            if (MODE == 1) {
                float dq = (o + (-16.0f)) * 6.528060436248779f;
                val = quantf(r + dq, 12.716455459594727f, -23.0f);
            } else if (MODE == 2) {
                val = o + r;
            } else {
                float res = o + r;
                val = (leakyf(res) + 34.0f) * 3.698859930038452f;
            }
            dst[l * C + c] = val;
        }
    }
}

// -------------------------------------------------------------------------
extern "C" void kernel_launch(void* const* d_in, const int* in_sizes, int n_in,
                              void* d_out, int out_size)
{
    (void)in_sizes; (void)n_in; (void)out_size;
    const float* x    = (const float*)d_in[0];
    const float* fb   = (const float*)d_in[1];
    const float* r1b  = (const float*)d_in[2];
    const float* r2b  = (const float*)d_in[3];
    const float* r3b  = (const float*)d_in[4];
    const float* wf   = (const float*)d_in[5];
    const float* bf   = (const float*)d_in[6];
    const float* wdw1 = (const float*)d_in[7],  *bdw1 = (const float*)d_in[8];
    const float* wpw1 = (const float*)d_in[9],  *bpw1 = (const float*)d_in[10];
    const float* wlc1 = (const float*)d_in[11], *blc1 = (const float*)d_in[12];
    const float* wdw2 = (const float*)d_in[13], *bdw2 = (const float*)d_in[14];
    const float* wpw2 = (const float*)d_in[15], *bpw2 = (const float*)d_in[16];
    const float* wlc2 = (const float*)d_in[17], *blc2 = (const float*)d_in[18];
    const float* wdw3 = (const float*)d_in[19], *bdw3 = (const float*)d_in[20];
    const float* wpw3 = (const float*)d_in[21], *bpw3 = (const float*)d_in[22];
    const float* wlc3 = (const float*)d_in[23], *blc3 = (const float*)d_in[24];
    float* out = (float*)d_out;

    float *bufA = nullptr, *bufB = nullptr;
    cudaGetSymbolAddress((void**)&bufA, g_bufA);
    cudaGetSymbolAddress((void**)&bufB, g_bufB);

    const int SM11 = ((TL + 2)  * C + TL * C) * 4;   // 133120 B
    const int SM23 = ((TL + 6)  * C + TL * C) * 4;   // 137216 B
    const int SM39 = ((TL + 18) * C + TL * C) * 4;   // 149504 B
    cudaFuncSetAttribute(k_block<1, 1>, cudaFuncAttributeMaxDynamicSharedMemorySize, SM11);
    cudaFuncSetAttribute(k_block<2, 3>, cudaFuncAttributeMaxDynamicSharedMemorySize, SM23);
    cudaFuncSetAttribute(k_block<3, 9>, cudaFuncAttributeMaxDynamicSharedMemorySize, SM39);

    const int NBLK = LFRAMES / TL;  // 1875, exact

    k_first<<<NBLK, NTH>>>(x, fb, wf, bf, bufA);
    k_block<1, 1><<<NBLK, NTH, SM11>>>(bufA, r1b, wdw1, bdw1, wpw1, bpw1, wlc1, blc1, bufB);
    k_block<2, 3><<<NBLK, NTH, SM23>>>(bufB, r2b, wdw2, bdw2, wpw2, bpw2, wlc2, blc2, bufA);
    k_block<3, 9><<<NBLK, NTH, SM39>>>(bufA, r3b, wdw3, bdw3, wpw3, bpw3, wlc3, blc3, out);
}

// round 2
// speedup vs baseline: 1.0822x; 1.0822x over previous
#include <cuda_runtime.h>

#define LFRAMES 120000
#define C       256
#define TL      64
#define NTH     256
#define TSAMP   600000
#define HSTRIDE 68   // padded stride for transposed H (16B aligned, reduces conflicts)

// ping-pong scratch for res_in between stages (static device arrays: allowed)
__device__ float g_bufA[LFRAMES * C];
__device__ float g_bufB[LFRAMES * C];

typedef unsigned long long u64;

__device__ __forceinline__ float leakyf(float x) { return x >= 0.0f ? x : 0.3f * x; }

__device__ __forceinline__ float quantf(float x, float s, float o) {
    float q = rintf(x / s - o);
    return fminf(fmaxf(q, -128.0f), 127.0f);
}

// packed f32x2 helpers (sm_103a)
__device__ __forceinline__ u64 pk2(float lo, float hi) {
    u64 r; asm("mov.b64 %0, {%1, %2};" : "=l"(r) : "f"(lo), "f"(hi)); return r;
}
__device__ __forceinline__ u64 ffma2(u64 a, u64 b, u64 c) {
    u64 d; asm("fma.rn.f32x2 %0, %1, %2, %3;" : "=l"(d) : "l"(a), "l"(b), "l"(c)); return d;
}
__device__ __forceinline__ float2 up2(u64 v) {
    float2 r; asm("mov.b64 {%0, %1}, %2;" : "=f"(r.x), "=f"(r.y) : "l"(v)); return r;
}

// -------------------------------------------------------------------------
// Kernel 1: first conv  (k=10, stride=5, cin=1 -> cout=256) + bias
// -------------------------------------------------------------------------
__global__ __launch_bounds__(NTH) void k_first(
    const float* __restrict__ x, const float* __restrict__ fb,
    const float* __restrict__ wf, const float* __restrict__ bf,
    float* __restrict__ out)
{
    __shared__ float sx[5 * TL + 10];
    const int l0  = blockIdx.x * TL;
    const int tid = threadIdx.x;
    const int base = 5 * l0;

    for (int i = tid; i < 5 * TL + 10; i += NTH) {
        int t = base + i;
        float v;
        if (t < 5)                 v = fb[t];
        else if (t - 5 < TSAMP)    v = x[t - 5];
        else                       v = 0.0f;
        sx[i] = v;
    }

    float w[10];
#pragma unroll
    for (int k = 0; k < 10; k++) w[k] = wf[k * C + tid];
    const float b = bf[tid];
    __syncthreads();

    for (int f = 0; f < TL; f++) {
        float acc = b;
#pragma unroll
        for (int k = 0; k < 10; k++) acc = fmaf(sx[5 * f + k], w[k], acc);
        out[(l0 + f) * C + tid] = acc;
    }
}

// -------------------------------------------------------------------------
// 256-deep GEMM with packed f32x2 FMAs.
// acc[i][j] holds output (row ty*8+i, cols tx*8+2j .. +2j+1) as packed f32x2.
// TRANS=true : sIn is H^T, layout [k][r] with row stride HSTRIDE.
// TRANS=false: sIn is row-major [r][C].
// Weights staged through sW in 32-row chunks.
// -------------------------------------------------------------------------
template <bool TRANS>
__device__ __forceinline__ void gemm256(
    u64 acc[8][4], const float* __restrict__ sIn, float* sW,
    const float* __restrict__ Wg, int ty, int tx, int tid)
{
    for (int kb = 0; kb < 8; kb++) {
        __syncthreads();  // previous users of sW done
        const float4* wg  = (const float4*)(Wg + kb * 32 * C);
        float4*       sw4 = (float4*)sW;
#pragma unroll
        for (int i = 0; i < 8; i++) sw4[tid + i * NTH] = wg[tid + i * NTH];
        __syncthreads();

#pragma unroll 4
        for (int kk = 0; kk < 32; kk++) {
            const int k = kb * 32 + kk;
            u64 hh[8];
            if (TRANS) {
                const float4* hp = (const float4*)(sIn + k * HSTRIDE + ty * 8);
                float4 ha = hp[0], hb = hp[1];
                hh[0] = pk2(ha.x, ha.x); hh[1] = pk2(ha.y, ha.y);
                hh[2] = pk2(ha.z, ha.z); hh[3] = pk2(ha.w, ha.w);
                hh[4] = pk2(hb.x, hb.x); hh[5] = pk2(hb.y, hb.y);
                hh[6] = pk2(hb.z, hb.z); hh[7] = pk2(hb.w, hb.w);
            } else {
#pragma unroll
                for (int i = 0; i < 8; i++) {
                    float h = sIn[(ty * 8 + i) * C + k];  // broadcast
                    hh[i] = pk2(h, h);
                }
            }
            const u64* w2 = (const u64*)(sW + kk * C + tx * 8);
            u64 ww0 = w2[0], ww1 = w2[1], ww2 = w2[2], ww3 = w2[3];
#pragma unroll
            for (int i = 0; i < 8; i++) {
                acc[i][0] = ffma2(hh[i], ww0, acc[i][0]);
                acc[i][1] = ffma2(hh[i], ww1, acc[i][1]);
                acc[i][2] = ffma2(hh[i], ww2, acc[i][2]);
                acc[i][3] = ffma2(hh[i], ww3, acc[i][3]);
            }
        }
    }
}

// -------------------------------------------------------------------------
// Fused residual block (modes as in R1).
// smem: sA = ci (TL+PAD rows x C) reused as weight staging (needs 8K floats)
//       sB = H^T (C x HSTRIDE) then P (TL x C)
// -------------------------------------------------------------------------
template <int MODE, int DIL>
__global__ __launch_bounds__(NTH) void k_block(
    const float* __restrict__ src,  const float* __restrict__ cbuf,
    const float* __restrict__ wdw,  const float* __restrict__ bdw,
    const float* __restrict__ wpw,  const float* __restrict__ bpw,
    const float* __restrict__ wlc,  const float* __restrict__ blc,
    float* __restrict__ dst)
{
    constexpr int PAD = 2 * DIL;
    constexpr float S2 = 5.548006534576416f;
    constexpr float S3 = 4.458680152893066f;

    extern __shared__ float sm[];
    float* sA = sm;                       // (TL+PAD)*C : ci, then W chunks
    float* sB = sm + (TL + PAD) * C;      // C*HSTRIDE  : H^T, then P[TL][C]

    const int l0  = blockIdx.x * TL;
    const int tid = threadIdx.x;
    const int ty  = tid >> 5;
    const int tx  = tid & 31;

    // 1) build ci tile (rows t = l0-PAD .. l0+TL-1), channel = tid
    for (int row = 0; row < TL + PAD; row++) {
        const int t = l0 - PAD + row;
        float v;
        if (t < 0) {
            float bv = cbuf[(t + PAD) * C + tid];
            if (MODE == 1)      v = bv;
            else if (MODE == 2) v = quantf(bv, S2, 47.0f);
            else                v = quantf(bv, S3, 38.0f);
        } else {
            float r = src[t * C + tid];
            if (MODE == 1) {
                v = leakyf(r);
            } else if (MODE == 2) {
                float d = (leakyf(r) + 47.0f) * S2;
                v = quantf(d, S2, 47.0f);
            } else {
                float d = (leakyf(r) + 38.0f) * S3;
                v = quantf(d, S3, 38.0f);
            }
        }
        sA[row * C + tid] = v;
    }
    __syncthreads();

    // 2) depthwise conv (k=3, dilation DIL) -> transposed H^T[ch][r]
    {
        const float w0 = wdw[tid], w1 = wdw[C + tid], w2 = wdw[2 * C + tid];
        const float bb = bdw[tid];
        for (int r = 0; r < TL; r++) {
            float h = bb;
            h = fmaf(sA[r * C + tid],             w0, h);
            h = fmaf(sA[(r + DIL) * C + tid],     w1, h);
            h = fmaf(sA[(r + 2 * DIL) * C + tid], w2, h);
            sB[tid * HSTRIDE + r] = h;
        }
    }
    __syncthreads();

    // 3) GEMM1: P = H @ Wpw + bpw   (input transposed)
    u64 acc[8][4];
    {
        const u64* b2 = (const u64*)(bpw + tx * 8);
        u64 b0 = b2[0], b1 = b2[1], b2v = b2[2], b3 = b2[3];
#pragma unroll
        for (int i = 0; i < 8; i++) {
            acc[i][0] = b0; acc[i][1] = b1; acc[i][2] = b2v; acc[i][3] = b3;
        }
    }
    gemm256<true>(acc, sB, sA, wpw, ty, tx, tid);
    __syncthreads();  // all reads of sB (H^T) done

    // 3b) pointwise epilogue -> write P (row-major) into sB
#pragma unroll
    for (int i = 0; i < 8; i++) {
#pragma unroll
        for (int j = 0; j < 4; j++) {
            float2 p = up2(acc[i][j]);
            if (MODE == 1) {
                p.x = quantf(p.x, 17.62967872619629f, -67.0f);
                p.y = quantf(p.y, 17.62967872619629f, -67.0f);
            }
            p.x = leakyf(p.x); p.y = leakyf(p.y);
            ((float2*)(sB + (ty * 8 + i) * C + tx * 8))[j] = p;
        }
    }
    __syncthreads();

    // 4) GEMM2: O = P @ Wlc + blc   (input row-major)
    {
        const u64* b2 = (const u64*)(blc + tx * 8);
        u64 b0 = b2[0], b1 = b2[1], b2v = b2[2], b3 = b2[3];
#pragma unroll
        for (int i = 0; i < 8; i++) {
            acc[i][0] = b0; acc[i][1] = b1; acc[i][2] = b2v; acc[i][3] = b3;
        }
    }
    gemm256<false>(acc, sB, sA, wlc, ty, tx, tid);

    // 5) residual + mode-specific output
#pragma unroll
    for (int i = 0; i < 8; i++) {
        const int l = l0 + ty * 8 + i;
#pragma unroll
        for (int j = 0; j < 4; j++) {
            float2 o = up2(acc[i][j]);
            const int c = tx * 8 + 2 * j;
            float2 r = *((const float2*)(src + l * C + c));
            float2 val;
            if (MODE == 1) {
                float dqx = (o.x - 16.0f) * 6.528060436248779f;
                float dqy = (o.y - 16.0f) * 6.528060436248779f;
                val.x = quantf(r.x + dqx, 12.716455459594727f, -23.0f);
                val.y = quantf(r.y + dqy, 12.716455459594727f, -23.0f);
            } else if (MODE == 2) {
                val.x = o.x + r.x;
                val.y = o.y + r.y;
            } else {
                val.x = (leakyf(o.x + r.x) + 34.0f) * 3.698859930038452f;
                val.y = (leakyf(o.y + r.y) + 34.0f) * 3.698859930038452f;
            }
            *((float2*)(dst + l * C + c)) = val;
        }
    }
}

// -------------------------------------------------------------------------
extern "C" void kernel_launch(void* const* d_in, const int* in_sizes, int n_in,
                              void* d_out, int out_size)
{
    (void)in_sizes; (void)n_in; (void)out_size;
    const float* x    = (const float*)d_in[0];
    const float* fb   = (const float*)d_in[1];
    const float* r1b  = (const float*)d_in[2];
    const float* r2b  = (const float*)d_in[3];
    const float* r3b  = (const float*)d_in[4];
    const float* wf   = (const float*)d_in[5];
    const float* bf   = (const float*)d_in[6];
    const float* wdw1 = (const float*)d_in[7],  *bdw1 = (const float*)d_in[8];
    const float* wpw1 = (const float*)d_in[9],  *bpw1 = (const float*)d_in[10];
    const float* wlc1 = (const float*)d_in[11], *blc1 = (const float*)d_in[12];
    const float* wdw2 = (const float*)d_in[13], *bdw2 = (const float*)d_in[14];
    const float* wpw2 = (const float*)d_in[15], *bpw2 = (const float*)d_in[16];
    const float* wlc2 = (const float*)d_in[17], *blc2 = (const float*)d_in[18];
    const float* wdw3 = (const float*)d_in[19], *bdw3 = (const float*)d_in[20];
    const float* wpw3 = (const float*)d_in[21], *bpw3 = (const float*)d_in[22];
    const float* wlc3 = (const float*)d_in[23], *blc3 = (const float*)d_in[24];
    float* out = (float*)d_out;

    float *bufA = nullptr, *bufB = nullptr;
    cudaGetSymbolAddress((void**)&bufA, g_bufA);
    cudaGetSymbolAddress((void**)&bufB, g_bufB);

    // smem = sA ((TL+PAD)*C) + sB (C*HSTRIDE)
    const int SM11 = ((TL + 2)  * C + C * HSTRIDE) * 4;
    const int SM23 = ((TL + 6)  * C + C * HSTRIDE) * 4;
    const int SM39 = ((TL + 18) * C + C * HSTRIDE) * 4;
    cudaFuncSetAttribute(k_block<1, 1>, cudaFuncAttributeMaxDynamicSharedMemorySize, SM11);
    cudaFuncSetAttribute(k_block<2, 3>, cudaFuncAttributeMaxDynamicSharedMemorySize, SM23);
    cudaFuncSetAttribute(k_block<3, 9>, cudaFuncAttributeMaxDynamicSharedMemorySize, SM39);

    const int NBLK = LFRAMES / TL;  // 1875

    k_first<<<NBLK, NTH>>>(x, fb, wf, bf, bufA);
    k_block<1, 1><<<NBLK, NTH, SM11>>>(bufA, r1b, wdw1, bdw1, wpw1, bpw1, wlc1, blc1, bufB);
    k_block<2, 3><<<NBLK, NTH, SM23>>>(bufB, r2b, wdw2, bdw2, wpw2, bpw2, wlc2, blc2, bufA);
    k_block<3, 9><<<NBLK, NTH, SM39>>>(bufA, r3b, wdw3, bdw3, wpw3, bpw3, wlc3, blc3, out);
}

// round 3
// speedup vs baseline: 1.1049x; 1.0209x over previous
#include <cuda_runtime.h>

#define LFRAMES 120000
#define C       256
#define TL      64
#define NTH     256
#define TSAMP   600000
#define HSTRIDE 68   // padded stride for transposed operands (16B aligned)

__device__ float g_bufA[LFRAMES * C];
__device__ float g_bufB[LFRAMES * C];

typedef unsigned long long u64;

__device__ __forceinline__ float leakyf(float x) { return x >= 0.0f ? x : 0.3f * x; }

__device__ __forceinline__ float quantf(float x, float s, float o) {
    float q = rintf(x / s - o);
    return fminf(fmaxf(q, -128.0f), 127.0f);
}

__device__ __forceinline__ u64 pk2(float lo, float hi) {
    u64 r; asm("mov.b64 %0, {%1, %2};" : "=l"(r) : "f"(lo), "f"(hi)); return r;
}
__device__ __forceinline__ u64 ffma2(u64 a, u64 b, u64 c) {
    u64 d; asm("fma.rn.f32x2 %0, %1, %2, %3;" : "=l"(d) : "l"(a), "l"(b), "l"(c)); return d;
}
__device__ __forceinline__ float2 up2(u64 v) {
    float2 r; asm("mov.b64 {%0, %1}, %2;" : "=f"(r.x), "=f"(r.y) : "l"(v)); return r;
}

// -------------------------------------------------------------------------
// Kernel 1: first conv  (k=10, stride=5, cin=1 -> cout=256) + bias
// -------------------------------------------------------------------------
__global__ __launch_bounds__(NTH) void k_first(
    const float* __restrict__ x, const float* __restrict__ fb,
    const float* __restrict__ wf, const float* __restrict__ bf,
    float* __restrict__ out)
{
    __shared__ float sx[5 * TL + 10];
    const int l0  = blockIdx.x * TL;
    const int tid = threadIdx.x;
    const int base = 5 * l0;

    for (int i = tid; i < 5 * TL + 10; i += NTH) {
        int t = base + i;
        float v;
        if (t < 5)                 v = fb[t];
        else if (t - 5 < TSAMP)    v = x[t - 5];
        else                       v = 0.0f;
        sx[i] = v;
    }

    float w[10];
#pragma unroll
    for (int k = 0; k < 10; k++) w[k] = wf[k * C + tid];
    const float b = bf[tid];
    __syncthreads();

    for (int f = 0; f < TL; f++) {
        float acc = b;
#pragma unroll
        for (int k = 0; k < 10; k++) acc = fmaf(sx[5 * f + k], w[k], acc);
        out[(l0 + f) * C + tid] = acc;
    }
}

// -------------------------------------------------------------------------
// 256-deep GEMM, packed f32x2 FMAs, transposed input operand.
// Thread (ty=tid>>5, tx=tid&31) owns rows ty*8..+7 and columns
//   group A: tx*4 + {0..3}   (acc[.][0], acc[.][1])
//   group B: 128 + tx*4 + {0..3} (acc[.][2], acc[.][3])
// sIn: transposed [k][r], row stride HSTRIDE (h loads = 2 broadcast LDS.128)
// Weight LDS.128 are 16B/lane contiguous across the warp (4 wavefronts).
// -------------------------------------------------------------------------
__device__ __forceinline__ void gemm256t(
    u64 acc[8][4], const float* __restrict__ sIn, float* sW,
    const float* __restrict__ Wg, int ty, int tx, int tid)
{
    for (int kb = 0; kb < 8; kb++) {
        __syncthreads();  // previous users of sW done
        const float4* wg  = (const float4*)(Wg + kb * 32 * C);
        float4*       sw4 = (float4*)sW;
#pragma unroll
        for (int i = 0; i < 8; i++) sw4[tid + i * NTH] = wg[tid + i * NTH];
        __syncthreads();

#pragma unroll 4
        for (int kk = 0; kk < 32; kk++) {
            const int k = kb * 32 + kk;
            const float4* hp = (const float4*)(sIn + k * HSTRIDE + ty * 8);
            float4 ha = hp[0], hb = hp[1];
            u64 hh[8];
            hh[0] = pk2(ha.x, ha.x); hh[1] = pk2(ha.y, ha.y);
            hh[2] = pk2(ha.z, ha.z); hh[3] = pk2(ha.w, ha.w);
            hh[4] = pk2(hb.x, hb.x); hh[5] = pk2(hb.y, hb.y);
            hh[6] = pk2(hb.z, hb.z); hh[7] = pk2(hb.w, hb.w);
            const u64* wA = (const u64*)(sW + kk * C + tx * 4);
            const u64* wB = (const u64*)(sW + kk * C + 128 + tx * 4);
            u64 ww0 = wA[0], ww1 = wA[1], ww2 = wB[0], ww3 = wB[1];
#pragma unroll
            for (int i = 0; i < 8; i++) {
                acc[i][0] = ffma2(hh[i], ww0, acc[i][0]);
                acc[i][1] = ffma2(hh[i], ww1, acc[i][1]);
                acc[i][2] = ffma2(hh[i], ww2, acc[i][2]);
                acc[i][3] = ffma2(hh[i], ww3, acc[i][3]);
            }
        }
    }
}

// -------------------------------------------------------------------------
// Fused residual block.
// smem: sA = ci (TL+PAD x C), reused as 32x256 weight staging
//       sB = H^T / P^T (C x HSTRIDE)
// -------------------------------------------------------------------------
template <int MODE, int DIL>
__global__ __launch_bounds__(NTH) void k_block(
    const float* __restrict__ src,  const float* __restrict__ cbuf,
    const float* __restrict__ wdw,  const float* __restrict__ bdw,
    const float* __restrict__ wpw,  const float* __restrict__ bpw,
    const float* __restrict__ wlc,  const float* __restrict__ blc,
    float* __restrict__ dst)
{
    constexpr int PAD = 2 * DIL;
    constexpr float S2 = 5.548006534576416f;
    constexpr float S3 = 4.458680152893066f;

    extern __shared__ float sm[];
    float* sA = sm;                       // (TL+PAD)*C : ci, then W chunks
    float* sB = sm + (TL + PAD) * C;      // C*HSTRIDE  : H^T then P^T

    const int l0  = blockIdx.x * TL;
    const int tid = threadIdx.x;
    const int ty  = tid >> 5;
    const int tx  = tid & 31;

    // 1) build ci tile
    for (int row = 0; row < TL + PAD; row++) {
        const int t = l0 - PAD + row;
        float v;
        if (t < 0) {
            float bv = cbuf[(t + PAD) * C + tid];
            if (MODE == 1)      v = bv;
            else if (MODE == 2) v = quantf(bv, S2, 47.0f);
            else                v = quantf(bv, S3, 38.0f);
        } else {
            float r = src[t * C + tid];
            if (MODE == 1) {
                v = leakyf(r);
            } else if (MODE == 2) {
                float d = (leakyf(r) + 47.0f) * S2;
                v = quantf(d, S2, 47.0f);
            } else {
                float d = (leakyf(r) + 38.0f) * S3;
                v = quantf(d, S3, 38.0f);
            }
        }
        sA[row * C + tid] = v;
    }
    __syncthreads();

    // 2) depthwise conv -> H^T[ch][r]
    {
        const float w0 = wdw[tid], w1 = wdw[C + tid], w2 = wdw[2 * C + tid];
        const float bb = bdw[tid];
        for (int r = 0; r < TL; r++) {
            float h = bb;
            h = fmaf(sA[r * C + tid],             w0, h);
            h = fmaf(sA[(r + DIL) * C + tid],     w1, h);
            h = fmaf(sA[(r + 2 * DIL) * C + tid], w2, h);
            sB[tid * HSTRIDE + r] = h;
        }
    }
    __syncthreads();

    // 3) GEMM1: P = H @ Wpw + bpw
    u64 acc[8][4];
    {
        const u64* bA = (const u64*)(bpw + tx * 4);
        const u64* bB = (const u64*)(bpw + 128 + tx * 4);
        u64 b0 = bA[0], b1 = bA[1], b2 = bB[0], b3 = bB[1];
#pragma unroll
        for (int i = 0; i < 8; i++) {
            acc[i][0] = b0; acc[i][1] = b1; acc[i][2] = b2; acc[i][3] = b3;
        }
    }
    gemm256t(acc, sB, sA, wpw, ty, tx, tid);
    __syncthreads();  // all reads of H^T done

    // 3b) epilogue: activation, then store P TRANSPOSED into sB
#pragma unroll
    for (int jj = 0; jj < 4; jj++) {
        const int cbase = (jj < 2) ? (tx * 4 + 2 * jj) : (128 + tx * 4 + 2 * (jj - 2));
        float2 v[8];
#pragma unroll
        for (int i = 0; i < 8; i++) {
            float2 p = up2(acc[i][jj]);
            if (MODE == 1) {
                p.x = quantf(p.x, 17.62967872619629f, -67.0f);
                p.y = quantf(p.y, 17.62967872619629f, -67.0f);
            }
            p.x = leakyf(p.x); p.y = leakyf(p.y);
            v[i] = p;
        }
        float4* d0 = (float4*)(sB + cbase * HSTRIDE + ty * 8);
        float4* d1 = (float4*)(sB + (cbase + 1) * HSTRIDE + ty * 8);
        d0[0] = make_float4(v[0].x, v[1].x, v[2].x, v[3].x);
        d0[1] = make_float4(v[4].x, v[5].x, v[6].x, v[7].x);
        d1[0] = make_float4(v[0].y, v[1].y, v[2].y, v[3].y);
        d1[1] = make_float4(v[4].y, v[5].y, v[6].y, v[7].y);
    }
    __syncthreads();

    // 4) GEMM2: O = P @ Wlc + blc  (P^T in sB)
    {
        const u64* bA = (const u64*)(blc + tx * 4);
        const u64* bB = (const u64*)(blc + 128 + tx * 4);
        u64 b0 = bA[0], b1 = bA[1], b2 = bB[0], b3 = bB[1];
#pragma unroll
        for (int i = 0; i < 8; i++) {
            acc[i][0] = b0; acc[i][1] = b1; acc[i][2] = b2; acc[i][3] = b3;
        }
    }
    gemm256t(acc, sB, sA, wlc, ty, tx, tid);

    // 5) residual + output
#pragma unroll
    for (int i = 0; i < 8; i++) {
        const int l = l0 + ty * 8 + i;
#pragma unroll
        for (int jj = 0; jj < 4; jj++) {
            const int c = (jj < 2) ? (tx * 4 + 2 * jj) : (128 + tx * 4 + 2 * (jj - 2));
            float2 o = up2(acc[i][jj]);
            float2 r = *((const float2*)(src + l * C + c));
            float2 val;
            if (MODE == 1) {
                float dqx = (o.x - 16.0f) * 6.528060436248779f;
                float dqy = (o.y - 16.0f) * 6.528060436248779f;
                val.x = quantf(r.x + dqx, 12.716455459594727f, -23.0f);
                val.y = quantf(r.y + dqy, 12.716455459594727f, -23.0f);
            } else if (MODE == 2) {
                val.x = o.x + r.x;
                val.y = o.y + r.y;
            } else {
                val.x = (leakyf(o.x + r.x) + 34.0f) * 3.698859930038452f;
                val.y = (leakyf(o.y + r.y) + 34.0f) * 3.698859930038452f;
            }
            *((float2*)(dst + l * C + c)) = val;
        }
    }
}

// -------------------------------------------------------------------------
extern "C" void kernel_launch(void* const* d_in, const int* in_sizes, int n_in,
                              void* d_out, int out_size)
{
    (void)in_sizes; (void)n_in; (void)out_size;
    const float* x    = (const float*)d_in[0];
    const float* fb   = (const float*)d_in[1];
    const float* r1b  = (const float*)d_in[2];
    const float* r2b  = (const float*)d_in[3];
    const float* r3b  = (const float*)d_in[4];
    const float* wf   = (const float*)d_in[5];
    const float* bf   = (const float*)d_in[6];
    const float* wdw1 = (const float*)d_in[7],  *bdw1 = (const float*)d_in[8];
    const float* wpw1 = (const float*)d_in[9],  *bpw1 = (const float*)d_in[10];
    const float* wlc1 = (const float*)d_in[11], *blc1 = (const float*)d_in[12];
    const float* wdw2 = (const float*)d_in[13], *bdw2 = (const float*)d_in[14];
    const float* wpw2 = (const float*)d_in[15], *bpw2 = (const float*)d_in[16];
    const float* wlc2 = (const float*)d_in[17], *blc2 = (const float*)d_in[18];
    const float* wdw3 = (const float*)d_in[19], *bdw3 = (const float*)d_in[20];
    const float* wpw3 = (const float*)d_in[21], *bpw3 = (const float*)d_in[22];
    const float* wlc3 = (const float*)d_in[23], *blc3 = (const float*)d_in[24];
    float* out = (float*)d_out;

    float *bufA = nullptr, *bufB = nullptr;
    cudaGetSymbolAddress((void**)&bufA, g_bufA);
    cudaGetSymbolAddress((void**)&bufB, g_bufB);

    const int SM11 = ((TL + 2)  * C + C * HSTRIDE) * 4;
    const int SM23 = ((TL + 6)  * C + C * HSTRIDE) * 4;
    const int SM39 = ((TL + 18) * C + C * HSTRIDE) * 4;
    cudaFuncSetAttribute(k_block<1, 1>, cudaFuncAttributeMaxDynamicSharedMemorySize, SM11);
    cudaFuncSetAttribute(k_block<2, 3>, cudaFuncAttributeMaxDynamicSharedMemorySize, SM23);
    cudaFuncSetAttribute(k_block<3, 9>, cudaFuncAttributeMaxDynamicSharedMemorySize, SM39);

    const int NBLK = LFRAMES / TL;  // 1875

    k_first<<<NBLK, NTH>>>(x, fb, wf, bf, bufA);
    k_block<1, 1><<<NBLK, NTH, SM11>>>(bufA, r1b, wdw1, bdw1, wpw1, bpw1, wlc1, blc1, bufB);
    k_block<2, 3><<<NBLK, NTH, SM23>>>(bufB, r2b, wdw2, bdw2, wpw2, bpw2, wlc2, blc2, bufA);
    k_block<3, 9><<<NBLK, NTH, SM39>>>(bufA, r3b, wdw3, bdw3, wpw3, bpw3, wlc3, blc3, out);
}

// round 4
// speedup vs baseline: 1.6832x; 1.5234x over previous
#include <cuda_runtime.h>

#define LFRAMES 120000
#define C       256
#define TL      64
#define NTH     256
#define TSAMP   600000
#define HSTRIDE 68

__device__ float g_bufA[LFRAMES * C];   // res ping
__device__ float g_bufB[LFRAMES * C];   // res pong
__device__ float g_bufC[LFRAMES * C];   // ci stream (blocks 1,3)
__device__ float g_bufD[LFRAMES * C];   // ci stream (block 2)

typedef unsigned long long u64;

__device__ __forceinline__ float leakyf(float x) { return x >= 0.0f ? x : 0.3f * x; }

// exact-division quantize (reference-matching); used only in cold paths
__device__ __forceinline__ float quant_div(float x, float s, float o) {
    float q = rintf(x / s - o);
    return fminf(fmaxf(q, -128.0f), 127.0f);
}
// reciprocal-multiply quantize; only for continuous-valued inputs
__device__ __forceinline__ float quant_mul(float x, float is, float o) {
    float q = rintf(x * is - o);
    return fminf(fmaxf(q, -128.0f), 127.0f);
}

__device__ __forceinline__ u64 pk2(float lo, float hi) {
    u64 r; asm("mov.b64 %0, {%1, %2};" : "=l"(r) : "f"(lo), "f"(hi)); return r;
}
__device__ __forceinline__ u64 ffma2(u64 a, u64 b, u64 c) {
    u64 d; asm("fma.rn.f32x2 %0, %1, %2, %3;" : "=l"(d) : "l"(a), "l"(b), "l"(c)); return d;
}
__device__ __forceinline__ float2 up2(u64 v) {
    float2 r; asm("mov.b64 {%0, %1}, %2;" : "=f"(r.x), "=f"(r.y) : "l"(v)); return r;
}

// -------------------------------------------------------------------------
// Kernel 1: first conv (k=10, stride=5, 1->256) + bias; also emits ci1=leaky
// -------------------------------------------------------------------------
__global__ __launch_bounds__(NTH) void k_first(
    const float* __restrict__ x, const float* __restrict__ fb,
    const float* __restrict__ wf, const float* __restrict__ bf,
    float* __restrict__ res, float* __restrict__ ci)
{
    __shared__ float sx[5 * TL + 10];
    const int l0  = blockIdx.x * TL;
    const int tid = threadIdx.x;
    const int base = 5 * l0;

    for (int i = tid; i < 5 * TL + 10; i += NTH) {
        int t = base + i;
        float v;
        if (t < 5)                 v = fb[t];
        else if (t - 5 < TSAMP)    v = x[t - 5];
        else                       v = 0.0f;
        sx[i] = v;
    }

    float w[10];
#pragma unroll
    for (int k = 0; k < 10; k++) w[k] = wf[k * C + tid];
    const float b = bf[tid];
    __syncthreads();

    for (int f = 0; f < TL; f++) {
        float acc = b;
#pragma unroll
        for (int k = 0; k < 10; k++) acc = fmaf(sx[5 * f + k], w[k], acc);
        res[(l0 + f) * C + tid] = acc;
        ci[(l0 + f) * C + tid]  = leakyf(acc);
    }
}

// -------------------------------------------------------------------------
// 256-deep GEMM, packed f32x2 FMAs, transposed input operand in sB.
// -------------------------------------------------------------------------
__device__ __forceinline__ void gemm256t(
    u64 acc[8][4], const float* __restrict__ sIn, float* sW,
    const float* __restrict__ Wg, int ty, int tx, int tid)
{
    for (int kb = 0; kb < 8; kb++) {
        __syncthreads();
        const float4* wg  = (const float4*)(Wg + kb * 32 * C);
        float4*       sw4 = (float4*)sW;
#pragma unroll
        for (int i = 0; i < 8; i++) sw4[tid + i * NTH] = wg[tid + i * NTH];
        __syncthreads();

#pragma unroll 4
        for (int kk = 0; kk < 32; kk++) {
            const int k = kb * 32 + kk;
            const float4* hp = (const float4*)(sIn + k * HSTRIDE + ty * 8);
            float4 ha = hp[0], hb = hp[1];
            u64 hh[8];
            hh[0] = pk2(ha.x, ha.x); hh[1] = pk2(ha.y, ha.y);
            hh[2] = pk2(ha.z, ha.z); hh[3] = pk2(ha.w, ha.w);
            hh[4] = pk2(hb.x, hb.x); hh[5] = pk2(hb.y, hb.y);
            hh[6] = pk2(hb.z, hb.z); hh[7] = pk2(hb.w, hb.w);
            const u64* wA = (const u64*)(sW + kk * C + tx * 4);
            const u64* wB = (const u64*)(sW + kk * C + 128 + tx * 4);
            u64 ww0 = wA[0], ww1 = wA[1], ww2 = wB[0], ww3 = wB[1];
#pragma unroll
            for (int i = 0; i < 8; i++) {
                acc[i][0] = ffma2(hh[i], ww0, acc[i][0]);
                acc[i][1] = ffma2(hh[i], ww1, acc[i][1]);
                acc[i][2] = ffma2(hh[i], ww2, acc[i][2]);
                acc[i][3] = ffma2(hh[i], ww3, acc[i][3]);
            }
        }
    }
}

// -------------------------------------------------------------------------
// Fused residual block. ci is read from a precomputed global stream.
// smem layout: [LUT 256][sW 32*256][sB C*HSTRIDE]  ~103KB -> 2 CTAs/SM
// -------------------------------------------------------------------------
template <int MODE, int DIL>
__global__ __launch_bounds__(NTH, 2) void k_block(
    const float* __restrict__ src,  const float* __restrict__ ciG,
    const float* __restrict__ cbuf,
    const float* __restrict__ wdw,  const float* __restrict__ bdw,
    const float* __restrict__ wpw,  const float* __restrict__ bpw,
    const float* __restrict__ wlc,  const float* __restrict__ blc,
    float* __restrict__ dst,        float* __restrict__ ciOut)
{
    constexpr int PAD = 2 * DIL;
    constexpr float S2 = 5.548006534576416f;
    constexpr float S3 = 4.458680152893066f;
    constexpr float INV_Q1  = (float)(1.0 / 17.62967872619629);
    constexpr float INV_RQ1 = (float)(1.0 / 12.716455459594727);
    constexpr float INV_S3  = (float)(1.0 / 4.458680152893066);

    extern __shared__ float sm[];
    float* sLUT = sm;              // 256
    float* sW   = sm + 256;        // 32*C
    float* sB   = sm + 256 + 32 * C;  // C*HSTRIDE

    const int l0  = blockIdx.x * TL;
    const int tid = threadIdx.x;
    const int ty  = tid >> 5;
    const int tx  = tid & 31;

    // LUT for MODE1's ci2 emission: n -> quant(dequant(leaky(n))) exact
    if (MODE == 1) {
        float n = (float)(tid - 128);
        float v = leakyf(n);
        float d = (v + 47.0f) * S2;
        sLUT[tid] = quant_div(d, S2, 47.0f);
    }

    // 1) depthwise conv (k=3, dilation DIL) from global ci stream -> H^T
    {
        const float w0 = wdw[tid], w1 = wdw[C + tid], w2 = wdw[2 * C + tid];
        const float bb = bdw[tid];
        for (int r = 0; r < TL; r++) {
            const int t0 = l0 + r - 2 * DIL;
            const int t1 = l0 + r - DIL;
            float c0, c1;
            if (t0 >= 0) c0 = ciG[t0 * C + tid];
            else {
                float bv = cbuf[(t0 + PAD) * C + tid];
                c0 = (MODE == 1) ? bv : (MODE == 2 ? quant_div(bv, S2, 47.0f)
                                                   : quant_div(bv, S3, 38.0f));
            }
            if (t1 >= 0) c1 = ciG[t1 * C + tid];
            else {
                float bv = cbuf[(t1 + PAD) * C + tid];
                c1 = (MODE == 1) ? bv : (MODE == 2 ? quant_div(bv, S2, 47.0f)
                                                   : quant_div(bv, S3, 38.0f));
            }
            float c2 = ciG[(l0 + r) * C + tid];
            float h = bb;
            h = fmaf(c0, w0, h);
            h = fmaf(c1, w1, h);
            h = fmaf(c2, w2, h);
            sB[tid * HSTRIDE + r] = h;
        }
    }
    __syncthreads();

    // 2) GEMM1: P = H @ Wpw + bpw
    u64 acc[8][4];
    {
        const u64* bA = (const u64*)(bpw + tx * 4);
        const u64* bB = (const u64*)(bpw + 128 + tx * 4);
        u64 b0 = bA[0], b1 = bA[1], b2 = bB[0], b3 = bB[1];
#pragma unroll
        for (int i = 0; i < 8; i++) {
            acc[i][0] = b0; acc[i][1] = b1; acc[i][2] = b2; acc[i][3] = b3;
        }
    }
    gemm256t(acc, sB, sW, wpw, ty, tx, tid);
    __syncthreads();

    // 2b) epilogue: activation, store P transposed
#pragma unroll
    for (int jj = 0; jj < 4; jj++) {
        const int cbase = (jj < 2) ? (tx * 4 + 2 * jj) : (128 + tx * 4 + 2 * (jj - 2));
        float2 v[8];
#pragma unroll
        for (int i = 0; i < 8; i++) {
            float2 p = up2(acc[i][jj]);
            if (MODE == 1) {
                p.x = quant_mul(p.x, INV_Q1, -67.0f);   // continuous input: recip OK
                p.y = quant_mul(p.y, INV_Q1, -67.0f);
            }
            p.x = leakyf(p.x); p.y = leakyf(p.y);
            v[i] = p;
        }
        float4* d0 = (float4*)(sB + cbase * HSTRIDE + ty * 8);
        float4* d1 = (float4*)(sB + (cbase + 1) * HSTRIDE + ty * 8);
        d0[0] = make_float4(v[0].x, v[1].x, v[2].x, v[3].x);
        d0[1] = make_float4(v[4].x, v[5].x, v[6].x, v[7].x);
        d1[0] = make_float4(v[0].y, v[1].y, v[2].y, v[3].y);
        d1[1] = make_float4(v[4].y, v[5].y, v[6].y, v[7].y);
    }
    __syncthreads();

    // 3) GEMM2: O = P @ Wlc + blc
    {
        const u64* bA = (const u64*)(blc + tx * 4);
        const u64* bB = (const u64*)(blc + 128 + tx * 4);
        u64 b0 = bA[0], b1 = bA[1], b2 = bB[0], b3 = bB[1];
#pragma unroll
        for (int i = 0; i < 8; i++) {
            acc[i][0] = b0; acc[i][1] = b1; acc[i][2] = b2; acc[i][3] = b3;
        }
    }
    gemm256t(acc, sB, sW, wlc, ty, tx, tid);

    // 4) residual + outputs (+ next block's ci stream)
#pragma unroll
    for (int i = 0; i < 8; i++) {
        const int l = l0 + ty * 8 + i;
#pragma unroll
        for (int jj = 0; jj < 4; jj++) {
            const int c = (jj < 2) ? (tx * 4 + 2 * jj) : (128 + tx * 4 + 2 * (jj - 2));
            float2 o = up2(acc[i][jj]);
            float2 r = *((const float2*)(src + l * C + c));
            float2 val, civ;
            if (MODE == 1) {
                float dqx = (o.x - 16.0f) * 6.528060436248779f;
                float dqy = (o.y - 16.0f) * 6.528060436248779f;
                val.x = quant_mul(r.x + dqx, INV_RQ1, -23.0f);  // continuous: recip OK
                val.y = quant_mul(r.y + dqy, INV_RQ1, -23.0f);
                civ.x = sLUT[(int)val.x + 128];                  // discrete: exact LUT
                civ.y = sLUT[(int)val.y + 128];
            } else if (MODE == 2) {
                val.x = o.x + r.x;
                val.y = o.y + r.y;
                float dx = (leakyf(val.x) + 38.0f) * S3;         // continuous: recip OK
                float dy = (leakyf(val.y) + 38.0f) * S3;
                civ.x = quant_mul(dx, INV_S3, 38.0f);
                civ.y = quant_mul(dy, INV_S3, 38.0f);
            } else {
                val.x = (leakyf(o.x + r.x) + 34.0f) * 3.698859930038452f;
                val.y = (leakyf(o.y + r.y) + 34.0f) * 3.698859930038452f;
            }
            *((float2*)(dst + l * C + c)) = val;
            if (MODE != 3) *((float2*)(ciOut + l * C + c)) = civ;
        }
    }
}

// -------------------------------------------------------------------------
extern "C" void kernel_launch(void* const* d_in, const int* in_sizes, int n_in,
                              void* d_out, int out_size)
{
    (void)in_sizes; (void)n_in; (void)out_size;
    const float* x    = (const float*)d_in[0];
    const float* fb   = (const float*)d_in[1];
    const float* r1b  = (const float*)d_in[2];
    const float* r2b  = (const float*)d_in[3];
    const float* r3b  = (const float*)d_in[4];
    const float* wf   = (const float*)d_in[5];
    const float* bf   = (const float*)d_in[6];
    const float* wdw1 = (const float*)d_in[7],  *bdw1 = (const float*)d_in[8];
    const float* wpw1 = (const float*)d_in[9],  *bpw1 = (const float*)d_in[10];
    const float* wlc1 = (const float*)d_in[11], *blc1 = (const float*)d_in[12];
    const float* wdw2 = (const float*)d_in[13], *bdw2 = (const float*)d_in[14];
    const float* wpw2 = (const float*)d_in[15], *bpw2 = (const float*)d_in[16];
    const float* wlc2 = (const float*)d_in[17], *blc2 = (const float*)d_in[18];
    const float* wdw3 = (const float*)d_in[19], *bdw3 = (const float*)d_in[20];
    const float* wpw3 = (const float*)d_in[21], *bpw3 = (const float*)d_in[22];
    const float* wlc3 = (const float*)d_in[23], *blc3 = (const float*)d_in[24];
    float* out = (float*)d_out;

    float *bufA, *bufB, *bufC, *bufD;
    cudaGetSymbolAddress((void**)&bufA, g_bufA);
    cudaGetSymbolAddress((void**)&bufB, g_bufB);
    cudaGetSymbolAddress((void**)&bufC, g_bufC);
    cudaGetSymbolAddress((void**)&bufD, g_bufD);

    const int SMB = (256 + 32 * C + C * HSTRIDE) * 4;  // ~103.4 KB
    cudaFuncSetAttribute(k_block<1, 1>, cudaFuncAttributeMaxDynamicSharedMemorySize, SMB);
    cudaFuncSetAttribute(k_block<2, 3>, cudaFuncAttributeMaxDynamicSharedMemorySize, SMB);
    cudaFuncSetAttribute(k_block<3, 9>, cudaFuncAttributeMaxDynamicSharedMemorySize, SMB);

    const int NBLK = LFRAMES / TL;  // 1875

    k_first<<<NBLK, NTH>>>(x, fb, wf, bf, bufA, bufC);
    k_block<1, 1><<<NBLK, NTH, SMB>>>(bufA, bufC, r1b, wdw1, bdw1, wpw1, bpw1,
                                      wlc1, blc1, bufB, bufD);
    k_block<2, 3><<<NBLK, NTH, SMB>>>(bufB, bufD, r2b, wdw2, bdw2, wpw2, bpw2,
                                      wlc2, blc2, bufA, bufC);
    k_block<3, 9><<<NBLK, NTH, SMB>>>(bufA, bufC, r3b, wdw3, bdw3, wpw3, bpw3,
                                      wlc3, blc3, out, nullptr);
}